// round 13
// baseline (speedup 1.0000x reference)
#include <cuda_runtime.h>
#include <cuda_bf16.h>
#include <cstdint>

// Problem constants
#define Bb 8
#define NSEQ 1024
#define DIM 768
#define HEADS 12
#define HD 64
#define TOPK 100
#define SCALE_F 0.125f

#define MROWS (Bb*NSEQ)          // 8192
#define QKV_N (3*DIM)            // 2304
#define NHEAD (Bb*HEADS)         // 96
#define CAP 192

// ---------------- scratch (device-symbol access ONLY from device code) ----
__device__ __align__(16) float g_q[NHEAD*NSEQ*HD];     // fp32, pre-scaled
__device__ __align__(16) float g_k[NHEAD*NSEQ*HD];
__device__ __align__(16) float g_v[NHEAD*NSEQ*HD];
__device__ __align__(16) float g_wpt_hi[DIM*DIM], g_wpt_lo[DIM*DIM];   // Wproj^T
__device__ __align__(16) float g_ahi[MROWS*DIM], g_alo[MROWS*DIM];     // attn hi/lo
__device__ int   g_idx[(size_t)NHEAD*NSEQ*CAP];
__device__ float g_pv [(size_t)NHEAD*NSEQ*CAP];
__device__ int   g_cnt[NHEAD*NSEQ];

// ---------------- helpers ----------------
#define MMA_TF32(d, a, b)                                                   \
    asm volatile("mma.sync.aligned.m16n8k8.row.col.f32.tf32.tf32.f32 "      \
        "{%0,%1,%2,%3}, {%4,%5,%6,%7}, {%8,%9}, {%0,%1,%2,%3};"             \
        : "+f"((d)[0]), "+f"((d)[1]), "+f"((d)[2]), "+f"((d)[3])            \
        : "r"((a)[0]), "r"((a)[1]), "r"((a)[2]), "r"((a)[3]),               \
          "r"((b)[0]), "r"((b)[1]))

// split to uint32 bit patterns (R8-proven form)
__device__ __forceinline__ void tf32_split_u(float f, uint32_t& hi, uint32_t& lo) {
    uint32_t h;
    asm("cvt.rna.tf32.f32 %0, %1;" : "=r"(h) : "f"(f));
    float hf = __uint_as_float(h);
    asm("cvt.rna.tf32.f32 %0, %1;" : "=r"(lo) : "f"(f - hf));
    hi = h;
}
__device__ __forceinline__ void tf32_split(float f, float& hi, float& lo) {
    uint32_t h, l;
    tf32_split_u(f, h, l);
    hi = __uint_as_float(h);
    lo = __uint_as_float(l);
}

// ---------------------------------------------------------------------------
// fp32 SGEMM (R4-PROVEN): QKV + scatter (q scaled) -> g_q/g_k/g_v
// ---------------------------------------------------------------------------
#define BM 128
#define BN 64
#define BK 16
#define TM 8
#define TN 4

__global__ __launch_bounds__(256)
void sgemm_kernel(const float* __restrict__ A, const float* __restrict__ B,
                  int M, int N, int K)
{
    __shared__ float As[2][BK][BM + 4];
    __shared__ float Bs[2][BK][BN];

    const int bm = blockIdx.y * BM;
    const int bn = blockIdx.x * BN;
    const int tid = threadIdx.x;
    const int tx = tid & 15;
    const int ty = tid >> 4;

    const int ar0 = tid >> 2;
    const int ar1 = (tid + 256) >> 2;
    const int ac4 = tid & 3;
    const int br  = tid >> 4;
    const int bc4 = tid & 15;

    const float* Abase0 = A + (size_t)(bm + ar0) * K + ac4 * 4;
    const float* Abase1 = A + (size_t)(bm + ar1) * K + ac4 * 4;
    const float* Bbase  = B + (size_t)br * N + bn + bc4 * 4;

    float acc[TM][TN];
#pragma unroll
    for (int i = 0; i < TM; i++)
#pragma unroll
        for (int j = 0; j < TN; j++) acc[i][j] = 0.f;

    {
        float4 a0 = *(const float4*)(Abase0);
        float4 a1 = *(const float4*)(Abase1);
        float4 b0 = *(const float4*)(Bbase);
        As[0][ac4*4+0][ar0] = a0.x; As[0][ac4*4+1][ar0] = a0.y;
        As[0][ac4*4+2][ar0] = a0.z; As[0][ac4*4+3][ar0] = a0.w;
        As[0][ac4*4+0][ar1] = a1.x; As[0][ac4*4+1][ar1] = a1.y;
        As[0][ac4*4+2][ar1] = a1.z; As[0][ac4*4+3][ar1] = a1.w;
        *(float4*)&Bs[0][br][bc4 * 4] = b0;
    }
    __syncthreads();

    const int nk = K / BK;
    for (int it = 0; it < nk; it++) {
        const int cur = it & 1;
        float4 pa0, pa1, pb;
        if (it + 1 < nk) {
            int k0 = (it + 1) * BK;
            pa0 = *(const float4*)(Abase0 + k0);
            pa1 = *(const float4*)(Abase1 + k0);
            pb  = *(const float4*)(Bbase + (size_t)k0 * N);
        }

#pragma unroll
        for (int kk = 0; kk < BK; kk++) {
            float a[TM], b[TN];
            float4 a40 = *(const float4*)&As[cur][kk][ty * TM + 0];
            float4 a41 = *(const float4*)&As[cur][kk][ty * TM + 4];
            a[0]=a40.x; a[1]=a40.y; a[2]=a40.z; a[3]=a40.w;
            a[4]=a41.x; a[5]=a41.y; a[6]=a41.z; a[7]=a41.w;
            float4 b4 = *(const float4*)&Bs[cur][kk][tx * TN];
            b[0]=b4.x; b[1]=b4.y; b[2]=b4.z; b[3]=b4.w;
#pragma unroll
            for (int i = 0; i < TM; i++)
#pragma unroll
                for (int j = 0; j < TN; j++)
                    acc[i][j] += a[i] * b[j];
        }

        if (it + 1 < nk) {
            const int nxt = 1 - cur;
            As[nxt][ac4*4+0][ar0] = pa0.x; As[nxt][ac4*4+1][ar0] = pa0.y;
            As[nxt][ac4*4+2][ar0] = pa0.z; As[nxt][ac4*4+3][ar0] = pa0.w;
            As[nxt][ac4*4+0][ar1] = pa1.x; As[nxt][ac4*4+1][ar1] = pa1.y;
            As[nxt][ac4*4+2][ar1] = pa1.z; As[nxt][ac4*4+3][ar1] = pa1.w;
            *(float4*)&Bs[nxt][br][bc4 * 4] = pb;
            __syncthreads();
        }
    }

#pragma unroll
    for (int i = 0; i < TM; i++) {
        int m  = bm + ty * TM + i;
        int b_ = m >> 10;
        int n_ = m & 1023;
#pragma unroll
        for (int j = 0; j < TN; j++) {
            int col = bn + tx * TN + j;
            int t = col / DIM;
            int r = col - t * DIM;
            int h = r >> 6;
            int d = r & 63;
            float vv = acc[i][j];
            float* dst;
            if (t == 0)      { dst = g_q; vv *= SCALE_F; }
            else if (t == 1)   dst = g_k;
            else               dst = g_v;
            dst[((size_t)((b_ * HEADS + h) << 10) + n_) * HD + d] = vv;
        }
    }
}

// ---------------------------------------------------------------------------
// Transpose + split W_proj[K][N] -> g_wpt [N][K] tf32 hi/lo (R12-PROVEN)
// ---------------------------------------------------------------------------
__global__ __launch_bounds__(256)
void transpose_split_wp(const float* __restrict__ W, int K, int N)
{
    __shared__ float tb[32][33];
    const int tx = threadIdx.x, ty = threadIdx.y;
    const int n0 = blockIdx.x * 32, k0 = blockIdx.y * 32;
#pragma unroll
    for (int i = 0; i < 4; i++)
        tb[ty + i*8][tx] = W[(size_t)(k0 + ty + i*8) * N + n0 + tx];
    __syncthreads();
#pragma unroll
    for (int i = 0; i < 4; i++) {
        float v = tb[tx][ty + i*8];
        int n = n0 + ty + i*8, k = k0 + tx;
        float h, l;
        tf32_split(v, h, l);
        g_wpt_hi[(size_t)n * K + k] = h;
        g_wpt_lo[(size_t)n * K + k] = l;
    }
}

// ---------------------------------------------------------------------------
// FUSED: S = Q@K^T (3xTF32, R8-proven mma layout, in-loop cvt) into SMEM,
// then exact top-100 threshold + masked softmax + compaction — no S in DRAM.
// CTA = 32 rows x 1024 cols of one head. 512 thr, 16 warps; warp owns an
// 8-col strip of each 128-col K chunk.
// ---------------------------------------------------------------------------
#define FROWS 32
#define FQS 68
#define FKS 68
#define FSS 1032
#define F_SMEM ((FROWS*FQS + 128*FKS + FROWS*FSS) * 4)   // 175616 B

__device__ __forceinline__ float ord2f(unsigned k) {
    unsigned u = (k & 0x80000000u) ? (k & 0x7FFFFFFFu) : ~k;
    return __uint_as_float(u);
}

__global__ __launch_bounds__(512)
void fused_s_topk()
{
    extern __shared__ float sm[];
    float* sQ = sm;                    // [32][68]
    float* sK = sm + FROWS * FQS;      // [128][68]
    float* sS = sK + 128 * FKS;        // [32][1032]

    const int tid  = threadIdx.x;
    const int wid  = tid >> 5;
    const int lane = tid & 31;
    const int gid  = lane >> 2;
    const int tig  = lane & 3;
    const int n0   = blockIdx.x * FROWS;
    const int head = blockIdx.y;
    const size_t off = (size_t)head * NSEQ * HD;

    // load Q tile (32x64)
    {
        int row = tid >> 4;
        int c4  = (tid & 15) * 4;
        *(float4*)&sQ[row * FQS + c4] =
            *(const float4*)(g_q + off + (size_t)(n0 + row) * HD + c4);
    }

    // ---- S phase: 8 chunks of 128 K-rows ----
    for (int c = 0; c < 8; c++) {
        __syncthreads();           // sK reuse guard; also publishes sQ (c==0)
#pragma unroll
        for (int t = 0; t < 4; t++) {
            int id  = tid + t * 512;
            int row = id >> 4;
            int c4  = (id & 15) * 4;
            *(float4*)&sK[row * FKS + c4] =
                *(const float4*)(g_k + off + (size_t)(c * 128 + row) * HD + c4);
        }
        __syncthreads();

        float d[2][4];
#pragma unroll
        for (int mi = 0; mi < 2; mi++)
#pragma unroll
            for (int e = 0; e < 4; e++) d[mi][e] = 0.f;

#pragma unroll
        for (int ks = 0; ks < 8; ks++) {
            const int k0 = ks * 8;
            // B fragments: n = wid*8 + gid
            uint32_t bh[2], bl[2];
            {
                const int nrow = wid * 8 + gid;
                tf32_split_u(sK[nrow * FKS + k0 + tig],     bh[0], bl[0]);
                tf32_split_u(sK[nrow * FKS + k0 + tig + 4], bh[1], bl[1]);
            }
#pragma unroll
            for (int mi = 0; mi < 2; mi++) {
                const int r0 = mi * 16 + gid;
                uint32_t ah[4], al[4];
                tf32_split_u(sQ[r0 * FQS + k0 + tig],           ah[0], al[0]);
                tf32_split_u(sQ[(r0 + 8) * FQS + k0 + tig],     ah[1], al[1]);
                tf32_split_u(sQ[r0 * FQS + k0 + tig + 4],       ah[2], al[2]);
                tf32_split_u(sQ[(r0 + 8) * FQS + k0 + tig + 4], ah[3], al[3]);
                MMA_TF32(d[mi], ah, bh);
                MMA_TF32(d[mi], ah, bl);
                MMA_TF32(d[mi], al, bh);
            }
        }

        // write chunk results to the smem S strip
#pragma unroll
        for (int mi = 0; mi < 2; mi++)
#pragma unroll
            for (int hf = 0; hf < 2; hf++) {
                int row = mi * 16 + gid + hf * 8;
                int col = c * 128 + wid * 8 + tig * 2;
                *(float2*)&sS[row * FSS + col] =
                    make_float2(d[mi][hf * 2 + 0], d[mi][hf * 2 + 1]);
            }
    }
    __syncthreads();

    // ---- top-k + softmax + compaction phase (PROVEN logic, smem source) ----
#pragma unroll
    for (int rr = 0; rr < 2; rr++) {
        const int row = wid * 2 + rr;
        const float* srow = sS + row * FSS;
        const size_t rbase = (size_t)head * NSEQ + n0 + row;

        float s[32];
#pragma unroll
        for (int i = 0; i < 32; i++) s[i] = srow[i * 32 + lane];

        unsigned lo = 0x007FFFFFu;
        unsigned hi = 0xFF800000u;
        while (lo < hi) {
            unsigned mid = lo + ((hi - lo + 1u) >> 1);
            float t = ord2f(mid);
            int cnt = 0;
#pragma unroll
            for (int i = 0; i < 32; i++) cnt += (s[i] >= t) ? 1 : 0;
#pragma unroll
            for (int o = 16; o > 0; o >>= 1)
                cnt += __shfl_xor_sync(0xffffffffu, cnt, o);
            if (cnt >= TOPK) lo = mid; else hi = mid - 1u;
        }
        const float kth = ord2f(lo);

        float m = s[0];
#pragma unroll
        for (int i = 1; i < 32; i++) m = fmaxf(m, s[i]);
#pragma unroll
        for (int o = 16; o > 0; o >>= 1)
            m = fmaxf(m, __shfl_xor_sync(0xffffffffu, m, o));

        float sum = 0.f;
        float p[32];
#pragma unroll
        for (int i = 0; i < 32; i++) {
            bool keep = (s[i] >= kth);
            p[i] = keep ? __expf(s[i] - m) : 0.f;
            sum += p[i];
        }
#pragma unroll
        for (int o = 16; o > 0; o >>= 1)
            sum += __shfl_xor_sync(0xffffffffu, sum, o);
        const float inv = 1.f / sum;

        int* oidx = g_idx + rbase * CAP;
        float* opv = g_pv + rbase * CAP;
        int base = 0;
#pragma unroll
        for (int i = 0; i < 32; i++) {
            bool keep = (p[i] > 0.f);
            unsigned msk = __ballot_sync(0xffffffffu, keep);
            int pos = base + __popc(msk & ((1u << lane) - 1u));
            if (keep && pos < CAP) {
                oidx[pos] = i * 32 + lane;
                opv[pos]  = p[i] * inv;
            }
            base += __popc(msk);
        }
        if (lane == 0) g_cnt[rbase] = (base < CAP) ? base : CAP;
    }
}

// ---------------------------------------------------------------------------
// sparse PV (PROVEN) -> attn hi/lo tf32 split (device symbols)
// ---------------------------------------------------------------------------
__global__ __launch_bounds__(256)
void pv_sparse_kernel()
{
    __shared__ int   sj[8][CAP];
    __shared__ float spv[8][CAP];

    const int head = blockIdx.y;
    const int warp = threadIdx.x >> 5;
    const int lane = threadIdx.x & 31;
    const int n    = blockIdx.x * 8 + warp;
    const size_t rbase = (size_t)head * NSEQ + n;

    const int cnt = g_cnt[rbase];
    const int* oidx = g_idx + rbase * CAP;
    const float* opv = g_pv + rbase * CAP;
    for (int i = lane; i < cnt; i += 32) {
        sj[warp][i]  = oidx[i];
        spv[warp][i] = opv[i];
    }
    __syncwarp();

    const float* V = g_v + (size_t)head * NSEQ * HD;
    float2 acc = make_float2(0.f, 0.f);
    const int d2 = lane * 2;

    int i = 0;
    for (; i + 4 <= cnt; i += 4) {
        int   j0 = sj[warp][i+0], j1 = sj[warp][i+1];
        int   j2 = sj[warp][i+2], j3 = sj[warp][i+3];
        float p0 = spv[warp][i+0], p1 = spv[warp][i+1];
        float p2 = spv[warp][i+2], p3 = spv[warp][i+3];
        float2 v0 = *(const float2*)(V + (size_t)j0 * HD + d2);
        float2 v1 = *(const float2*)(V + (size_t)j1 * HD + d2);
        float2 v2 = *(const float2*)(V + (size_t)j2 * HD + d2);
        float2 v3 = *(const float2*)(V + (size_t)j3 * HD + d2);
        acc.x += p0*v0.x + p1*v1.x + p2*v2.x + p3*v3.x;
        acc.y += p0*v0.y + p1*v1.y + p2*v2.y + p3*v3.y;
    }
    for (; i < cnt; i++) {
        int j = sj[warp][i];
        float pp = spv[warp][i];
        float2 v = *(const float2*)(V + (size_t)j * HD + d2);
        acc.x += pp * v.x;
        acc.y += pp * v.y;
    }

    const int b = head / HEADS;
    const int h = head - b * HEADS;
    const size_t o = ((size_t)(b * NSEQ + n)) * DIM + h * HD + d2;
    float h0, l0, h1, l1;
    tf32_split(acc.x, h0, l0);
    tf32_split(acc.y, h1, l1);
    *(float2*)(g_ahi + o) = make_float2(h0, h1);
    *(float2*)(g_alo + o) = make_float2(l0, l1);
}

// ---------------------------------------------------------------------------
// 3xTF32 proj GEMM (R12-PROVEN): out = attn @ Wp^T + bias
// ---------------------------------------------------------------------------
#define GSTR 20
#define GA_H 0
#define GA_L (128*GSTR*4)
#define GB_H (2*128*GSTR*4)
#define GB_L (3*128*GSTR*4)
#define GBUF (4*128*GSTR*4)           // 40960 B
#define G_SMEM (2*GBUF)               // 81920 B

__global__ __launch_bounds__(512)
void mma_proj_tf32(const float* __restrict__ bias, float* __restrict__ out)
{
    const float* Ahi = g_ahi;
    const float* Alo = g_alo;
    const float* Bhi = g_wpt_hi;
    const float* Blo = g_wpt_lo;
    const int K = DIM;

    extern __shared__ char smc[];
    const int tid  = threadIdx.x;
    const int wid  = tid >> 5;
    const int lane = tid & 31;
    const int gid  = lane >> 2;
    const int tig  = lane & 3;
    const int wm   = wid & 3;
    const int wn   = wid >> 2;
    const int bn   = blockIdx.x * 128;
    const int bm   = blockIdx.y * 128;

    const int lrow = tid >> 2;
    const int lko  = (tid & 3) * 4;
    const float* pAh = Ahi + (size_t)(bm + lrow) * K + lko;
    const float* pAl = Alo + (size_t)(bm + lrow) * K + lko;
    const float* pBh = Bhi + (size_t)(bn + lrow) * K + lko;
    const float* pBl = Blo + (size_t)(bn + lrow) * K + lko;
    const uint32_t soff = (uint32_t)(lrow * GSTR + lko) * 4;

    float d[2][4][4];
#pragma unroll
    for (int mi = 0; mi < 2; mi++)
#pragma unroll
        for (int nj = 0; nj < 4; nj++)
#pragma unroll
            for (int e = 0; e < 4; e++) d[mi][nj][e] = 0.f;

    const int ns = K >> 4;

    {
        *(float4*)(smc + GA_H + soff) = *(const float4*)(pAh);
        *(float4*)(smc + GA_L + soff) = *(const float4*)(pAl);
        *(float4*)(smc + GB_H + soff) = *(const float4*)(pBh);
        *(float4*)(smc + GB_L + soff) = *(const float4*)(pBl);
    }
    __syncthreads();

    for (int s = 0; s < ns; s++) {
        float4 pa0, pa1, pb0, pb1;
        if (s + 1 < ns) {
            const int k0 = (s + 1) << 4;
            pa0 = *(const float4*)(pAh + k0);
            pa1 = *(const float4*)(pAl + k0);
            pb0 = *(const float4*)(pBh + k0);
            pb1 = *(const float4*)(pBl + k0);
        }

        const char* buf = smc + (s & 1) * GBUF;
        const uint32_t* Ah32 = (const uint32_t*)(buf + GA_H);
        const uint32_t* Al32 = (const uint32_t*)(buf + GA_L);
        const uint32_t* Bh32 = (const uint32_t*)(buf + GB_H);
        const uint32_t* Bl32 = (const uint32_t*)(buf + GB_L);

#pragma unroll
        for (int ksub = 0; ksub < 2; ksub++) {
            const int k0c = ksub * 8;
            uint32_t ah[2][4], al[2][4], bh[4][2], bl[4][2];
#pragma unroll
            for (int mi = 0; mi < 2; mi++) {
                int r0 = wm * 32 + mi * 16 + gid;
                ah[mi][0] = Ah32[r0 * GSTR + k0c + tig];
                ah[mi][1] = Ah32[(r0 + 8) * GSTR + k0c + tig];
                ah[mi][2] = Ah32[r0 * GSTR + k0c + tig + 4];
                ah[mi][3] = Ah32[(r0 + 8) * GSTR + k0c + tig + 4];
                al[mi][0] = Al32[r0 * GSTR + k0c + tig];
                al[mi][1] = Al32[(r0 + 8) * GSTR + k0c + tig];
                al[mi][2] = Al32[r0 * GSTR + k0c + tig + 4];
                al[mi][3] = Al32[(r0 + 8) * GSTR + k0c + tig + 4];
            }
#pragma unroll
            for (int nj = 0; nj < 4; nj++) {
                int n = wn * 32 + nj * 8 + gid;
                bh[nj][0] = Bh32[n * GSTR + k0c + tig];
                bh[nj][1] = Bh32[n * GSTR + k0c + tig + 4];
                bl[nj][0] = Bl32[n * GSTR + k0c + tig];
                bl[nj][1] = Bl32[n * GSTR + k0c + tig + 4];
            }
#pragma unroll
            for (int mi = 0; mi < 2; mi++)
#pragma unroll
                for (int nj = 0; nj < 4; nj++) {
                    MMA_TF32(d[mi][nj], ah[mi], bh[nj]);
                    MMA_TF32(d[mi][nj], ah[mi], bl[nj]);
                    MMA_TF32(d[mi][nj], al[mi], bh[nj]);
                }
        }

        if (s + 1 < ns) {
            char* nbuf = smc + ((s + 1) & 1) * GBUF;
            *(float4*)(nbuf + GA_H + soff) = pa0;
            *(float4*)(nbuf + GA_L + soff) = pa1;
            *(float4*)(nbuf + GB_H + soff) = pb0;
            *(float4*)(nbuf + GB_L + soff) = pb1;
            __syncthreads();
        }
    }

#pragma unroll
    for (int mi = 0; mi < 2; mi++)
#pragma unroll
        for (int nj = 0; nj < 4; nj++)
#pragma unroll
            for (int hf = 0; hf < 2; hf++) {
                const int m   = bm + wm * 32 + mi * 16 + gid + hf * 8;
                const int col = bn + wn * 32 + nj * 8 + tig * 2;
                float* dst = out + (size_t)m * DIM + col;
                *(float2*)dst = make_float2(d[mi][nj][hf*2+0] + bias[col],
                                            d[mi][nj][hf*2+1] + bias[col+1]);
            }
}

// ---------------------------------------------------------------------------
extern "C" void kernel_launch(void* const* d_in, const int* in_sizes, int n_in,
                              void* d_out, int out_size)
{
    const float* x      = (const float*)d_in[0];
    const float* w_qkv  = (const float*)d_in[1];
    const float* w_proj = (const float*)d_in[2];
    const float* b_proj = (const float*)d_in[3];
    float* out = (float*)d_out;

    cudaFuncSetAttribute(fused_s_topk,
                         cudaFuncAttributeMaxDynamicSharedMemorySize, F_SMEM);
    cudaFuncSetAttribute(mma_proj_tf32,
                         cudaFuncAttributeMaxDynamicSharedMemorySize, G_SMEM);

    // 0) proj weight transpose+split
    transpose_split_wp<<<dim3(DIM / 32, DIM / 32), dim3(32, 8)>>>(w_proj, DIM, DIM);

    // 1) QKV GEMM (fp32, PROVEN) + scatter
    sgemm_kernel<<<dim3(QKV_N / BN, MROWS / BM), 256>>>(
        x, w_qkv, MROWS, QKV_N, DIM);

    // 2) FUSED S + top-k + softmax + compaction (S never leaves smem)
    fused_s_topk<<<dim3(NSEQ / FROWS, NHEAD), 512, F_SMEM>>>();

    // 3) sparse PV gather -> attn hi/lo
    pv_sparse_kernel<<<dim3(NSEQ / 8, NHEAD), 256>>>();

    // 4) output projection + bias (3xTF32, PROVEN)
    mma_proj_tf32<<<dim3(DIM / 128, MROWS / 128), 512, G_SMEM>>>(b_proj, out);
}

// round 14
// speedup vs baseline: 1.1311x; 1.1311x over previous
#include <cuda_runtime.h>
#include <cuda_bf16.h>
#include <cstdint>

// Problem constants
#define Bb 8
#define NSEQ 1024
#define DIM 768
#define HEADS 12
#define HD 64
#define TOPK 100
#define SCALE_F 0.125f

#define MROWS (Bb*NSEQ)          // 8192
#define QKV_N (3*DIM)            // 2304
#define QK_N  (2*DIM)            // 1536
#define NHEAD (Bb*HEADS)         // 96
#define CAP 192

// ---------------- scratch (device-symbol access ONLY from device code) ----
__device__ __align__(16) float g_q[NHEAD*NSEQ*HD];     // fp32, pre-scaled
__device__ __align__(16) float g_k[NHEAD*NSEQ*HD];
__device__ __align__(16) float g_v[NHEAD*NSEQ*HD];
__device__ __align__(16) float g_xhi[MROWS*DIM], g_xlo[MROWS*DIM];
__device__ __align__(16) float g_wvt_hi[DIM*DIM], g_wvt_lo[DIM*DIM];   // Wv^T
__device__ __align__(16) float g_wpt_hi[DIM*DIM], g_wpt_lo[DIM*DIM];   // Wproj^T
__device__ __align__(16) float g_ahi[MROWS*DIM], g_alo[MROWS*DIM];     // attn hi/lo
__device__ __align__(16) float g_s[(size_t)NHEAD*NSEQ*NSEQ];
__device__ int   g_idx[(size_t)NHEAD*NSEQ*CAP];
__device__ float g_pv [(size_t)NHEAD*NSEQ*CAP];
__device__ int   g_cnt[NHEAD*NSEQ];

// ---------------- helpers ----------------
#define MMA_TF32(d, a, b)                                                   \
    asm volatile("mma.sync.aligned.m16n8k8.row.col.f32.tf32.tf32.f32 "      \
        "{%0,%1,%2,%3}, {%4,%5,%6,%7}, {%8,%9}, {%0,%1,%2,%3};"             \
        : "+f"((d)[0]), "+f"((d)[1]), "+f"((d)[2]), "+f"((d)[3])            \
        : "r"((a)[0]), "r"((a)[1]), "r"((a)[2]), "r"((a)[3]),               \
          "r"((b)[0]), "r"((b)[1]))

__device__ __forceinline__ void tf32_split_u(float f, uint32_t& hi, uint32_t& lo) {
    uint32_t h;
    asm("cvt.rna.tf32.f32 %0, %1;" : "=r"(h) : "f"(f));
    float hf = __uint_as_float(h);
    asm("cvt.rna.tf32.f32 %0, %1;" : "=r"(lo) : "f"(f - hf));
    hi = h;
}
__device__ __forceinline__ void tf32_split(float f, float& hi, float& lo) {
    uint32_t h, l;
    tf32_split_u(f, h, l);
    hi = __uint_as_float(h);
    lo = __uint_as_float(l);
}
__device__ __forceinline__ unsigned f2ord(float f) {
    unsigned u = __float_as_uint(f);
    return (u & 0x80000000u) ? ~u : (u | 0x80000000u);
}
__device__ __forceinline__ float ord2f(unsigned k) {
    unsigned u = (k & 0x80000000u) ? (k & 0x7FFFFFFFu) : ~k;
    return __uint_as_float(u);
}
__device__ __forceinline__ int redux_add(int v) {
    int r;
    asm("redux.sync.add.s32 %0, %1, 0xffffffff;" : "=r"(r) : "r"(v));
    return r;
}
__device__ __forceinline__ unsigned redux_max_u(unsigned v) {
    unsigned r;
    asm("redux.sync.max.u32 %0, %1, 0xffffffff;" : "=r"(r) : "r"(v));
    return r;
}

// ---------------------------------------------------------------------------
// fp32 SGEMM (R4-PROVEN) for Q/K only: N=1536 output cols, B row stride ldB.
// Scatter epilogue (q scaled) -> g_q/g_k.
// ---------------------------------------------------------------------------
#define BM 128
#define BN 64
#define BK 16
#define TM 8
#define TN 4

__global__ __launch_bounds__(256)
void sgemm_qk(const float* __restrict__ A, const float* __restrict__ B,
              int M, int K, int ldB)
{
    __shared__ float As[2][BK][BM + 4];
    __shared__ float Bs[2][BK][BN];

    const int bm = blockIdx.y * BM;
    const int bn = blockIdx.x * BN;
    const int tid = threadIdx.x;
    const int tx = tid & 15;
    const int ty = tid >> 4;

    const int ar0 = tid >> 2;
    const int ar1 = (tid + 256) >> 2;
    const int ac4 = tid & 3;
    const int br  = tid >> 4;
    const int bc4 = tid & 15;

    const float* Abase0 = A + (size_t)(bm + ar0) * K + ac4 * 4;
    const float* Abase1 = A + (size_t)(bm + ar1) * K + ac4 * 4;
    const float* Bbase  = B + (size_t)br * ldB + bn + bc4 * 4;

    float acc[TM][TN];
#pragma unroll
    for (int i = 0; i < TM; i++)
#pragma unroll
        for (int j = 0; j < TN; j++) acc[i][j] = 0.f;

    {
        float4 a0 = *(const float4*)(Abase0);
        float4 a1 = *(const float4*)(Abase1);
        float4 b0 = *(const float4*)(Bbase);
        As[0][ac4*4+0][ar0] = a0.x; As[0][ac4*4+1][ar0] = a0.y;
        As[0][ac4*4+2][ar0] = a0.z; As[0][ac4*4+3][ar0] = a0.w;
        As[0][ac4*4+0][ar1] = a1.x; As[0][ac4*4+1][ar1] = a1.y;
        As[0][ac4*4+2][ar1] = a1.z; As[0][ac4*4+3][ar1] = a1.w;
        *(float4*)&Bs[0][br][bc4 * 4] = b0;
    }
    __syncthreads();

    const int nk = K / BK;
    for (int it = 0; it < nk; it++) {
        const int cur = it & 1;
        float4 pa0, pa1, pb;
        if (it + 1 < nk) {
            int k0 = (it + 1) * BK;
            pa0 = *(const float4*)(Abase0 + k0);
            pa1 = *(const float4*)(Abase1 + k0);
            pb  = *(const float4*)(Bbase + (size_t)k0 * ldB);
        }

#pragma unroll
        for (int kk = 0; kk < BK; kk++) {
            float a[TM], b[TN];
            float4 a40 = *(const float4*)&As[cur][kk][ty * TM + 0];
            float4 a41 = *(const float4*)&As[cur][kk][ty * TM + 4];
            a[0]=a40.x; a[1]=a40.y; a[2]=a40.z; a[3]=a40.w;
            a[4]=a41.x; a[5]=a41.y; a[6]=a41.z; a[7]=a41.w;
            float4 b4 = *(const float4*)&Bs[cur][kk][tx * TN];
            b[0]=b4.x; b[1]=b4.y; b[2]=b4.z; b[3]=b4.w;
#pragma unroll
            for (int i = 0; i < TM; i++)
#pragma unroll
                for (int j = 0; j < TN; j++)
                    acc[i][j] += a[i] * b[j];
        }

        if (it + 1 < nk) {
            const int nxt = 1 - cur;
            As[nxt][ac4*4+0][ar0] = pa0.x; As[nxt][ac4*4+1][ar0] = pa0.y;
            As[nxt][ac4*4+2][ar0] = pa0.z; As[nxt][ac4*4+3][ar0] = pa0.w;
            As[nxt][ac4*4+0][ar1] = pa1.x; As[nxt][ac4*4+1][ar1] = pa1.y;
            As[nxt][ac4*4+2][ar1] = pa1.z; As[nxt][ac4*4+3][ar1] = pa1.w;
            *(float4*)&Bs[nxt][br][bc4 * 4] = pb;
            __syncthreads();
        }
    }

#pragma unroll
    for (int i = 0; i < TM; i++) {
        int m  = bm + ty * TM + i;
        int b_ = m >> 10;
        int n_ = m & 1023;
#pragma unroll
        for (int j = 0; j < TN; j++) {
            int col = bn + tx * TN + j;     // < 1536: t in {0,1}
            int t = col / DIM;
            int r = col - t * DIM;
            int h = r >> 6;
            int d = r & 63;
            float vv = acc[i][j];
            float* dst;
            if (t == 0) { dst = g_q; vv *= SCALE_F; }
            else          dst = g_k;
            dst[((size_t)((b_ * HEADS + h) << 10) + n_) * HD + d] = vv;
        }
    }
}

// ---------------------------------------------------------------------------
// Split x -> tf32 hi/lo (R11-proven structure, device-symbol outputs)
// ---------------------------------------------------------------------------
__global__ __launch_bounds__(256)
void split_x_kernel(const float* __restrict__ x, int n4)
{
    int i = blockIdx.x * 256 + threadIdx.x;
    if (i >= n4) return;
    float4 v = ((const float4*)x)[i];
    float4 h4, l4;
    tf32_split(v.x, h4.x, l4.x);
    tf32_split(v.y, h4.y, l4.y);
    tf32_split(v.z, h4.z, l4.z);
    tf32_split(v.w, h4.w, l4.w);
    ((float4*)g_xhi)[i] = h4;
    ((float4*)g_xlo)[i] = l4;
}

// ---------------------------------------------------------------------------
// Transpose+split (R12-proven pattern). which 0: Wproj[768][768] -> g_wpt.
// which 1: Wqkv v-columns [768][2304] cols 1536.. -> g_wvt [768][768].
// ---------------------------------------------------------------------------
__global__ __launch_bounds__(256)
void transpose_split_w(const float* __restrict__ W, int ldW, int colOff, int which)
{
    float* Thi = which ? g_wvt_hi : g_wpt_hi;
    float* Tlo = which ? g_wvt_lo : g_wpt_lo;

    __shared__ float tb[32][33];
    const int tx = threadIdx.x, ty = threadIdx.y;
    const int n0 = blockIdx.x * 32, k0 = blockIdx.y * 32;
#pragma unroll
    for (int i = 0; i < 4; i++)
        tb[ty + i*8][tx] = W[(size_t)(k0 + ty + i*8) * ldW + colOff + n0 + tx];
    __syncthreads();
#pragma unroll
    for (int i = 0; i < 4; i++) {
        float v = tb[tx][ty + i*8];
        int n = n0 + ty + i*8, k = k0 + tx;
        float h, l;
        tf32_split(v, h, l);
        Thi[(size_t)n * DIM + k] = h;
        Tlo[(size_t)n * DIM + k] = l;
    }
}

// ---------------------------------------------------------------------------
// 3xTF32 GEMM core (R11/R12-PROVEN): D[128x128] tiles, K-chunk 16,
// register-staged double buffer. mode 0: V scatter; mode 1: proj bias->out.
// ---------------------------------------------------------------------------
#define GSTR 20
#define GA_H 0
#define GA_L (128*GSTR*4)
#define GB_H (2*128*GSTR*4)
#define GB_L (3*128*GSTR*4)
#define GBUF (4*128*GSTR*4)           // 40960 B
#define G_SMEM (2*GBUF)               // 81920 B

__global__ __launch_bounds__(512)
void mma_gemm_tf32(int mode, const float* __restrict__ bias,
                   float* __restrict__ out)
{
    const float* Ahi = (mode == 0) ? g_xhi : g_ahi;
    const float* Alo = (mode == 0) ? g_xlo : g_alo;
    const float* Bhi = (mode == 0) ? g_wvt_hi : g_wpt_hi;
    const float* Blo = (mode == 0) ? g_wvt_lo : g_wpt_lo;
    const int K = DIM;

    extern __shared__ char smc[];
    const int tid  = threadIdx.x;
    const int wid  = tid >> 5;
    const int lane = tid & 31;
    const int gid  = lane >> 2;
    const int tig  = lane & 3;
    const int wm   = wid & 3;
    const int wn   = wid >> 2;
    const int bn   = blockIdx.x * 128;
    const int bm   = blockIdx.y * 128;

    const int lrow = tid >> 2;
    const int lko  = (tid & 3) * 4;
    const float* pAh = Ahi + (size_t)(bm + lrow) * K + lko;
    const float* pAl = Alo + (size_t)(bm + lrow) * K + lko;
    const float* pBh = Bhi + (size_t)(bn + lrow) * K + lko;
    const float* pBl = Blo + (size_t)(bn + lrow) * K + lko;
    const uint32_t soff = (uint32_t)(lrow * GSTR + lko) * 4;

    float d[2][4][4];
#pragma unroll
    for (int mi = 0; mi < 2; mi++)
#pragma unroll
        for (int nj = 0; nj < 4; nj++)
#pragma unroll
            for (int e = 0; e < 4; e++) d[mi][nj][e] = 0.f;

    const int ns = K >> 4;

    {
        *(float4*)(smc + GA_H + soff) = *(const float4*)(pAh);
        *(float4*)(smc + GA_L + soff) = *(const float4*)(pAl);
        *(float4*)(smc + GB_H + soff) = *(const float4*)(pBh);
        *(float4*)(smc + GB_L + soff) = *(const float4*)(pBl);
    }
    __syncthreads();

    for (int s = 0; s < ns; s++) {
        float4 pa0, pa1, pb0, pb1;
        if (s + 1 < ns) {
            const int k0 = (s + 1) << 4;
            pa0 = *(const float4*)(pAh + k0);
            pa1 = *(const float4*)(pAl + k0);
            pb0 = *(const float4*)(pBh + k0);
            pb1 = *(const float4*)(pBl + k0);
        }

        const char* buf = smc + (s & 1) * GBUF;
        const uint32_t* Ah32 = (const uint32_t*)(buf + GA_H);
        const uint32_t* Al32 = (const uint32_t*)(buf + GA_L);
        const uint32_t* Bh32 = (const uint32_t*)(buf + GB_H);
        const uint32_t* Bl32 = (const uint32_t*)(buf + GB_L);

#pragma unroll
        for (int ksub = 0; ksub < 2; ksub++) {
            const int k0c = ksub * 8;
            uint32_t ah[2][4], al[2][4], bh[4][2], bl[4][2];
#pragma unroll
            for (int mi = 0; mi < 2; mi++) {
                int r0 = wm * 32 + mi * 16 + gid;
                ah[mi][0] = Ah32[r0 * GSTR + k0c + tig];
                ah[mi][1] = Ah32[(r0 + 8) * GSTR + k0c + tig];
                ah[mi][2] = Ah32[r0 * GSTR + k0c + tig + 4];
                ah[mi][3] = Ah32[(r0 + 8) * GSTR + k0c + tig + 4];
                al[mi][0] = Al32[r0 * GSTR + k0c + tig];
                al[mi][1] = Al32[(r0 + 8) * GSTR + k0c + tig];
                al[mi][2] = Al32[r0 * GSTR + k0c + tig + 4];
                al[mi][3] = Al32[(r0 + 8) * GSTR + k0c + tig + 4];
            }
#pragma unroll
            for (int nj = 0; nj < 4; nj++) {
                int n = wn * 32 + nj * 8 + gid;
                bh[nj][0] = Bh32[n * GSTR + k0c + tig];
                bh[nj][1] = Bh32[n * GSTR + k0c + tig + 4];
                bl[nj][0] = Bl32[n * GSTR + k0c + tig];
                bl[nj][1] = Bl32[n * GSTR + k0c + tig + 4];
            }
#pragma unroll
            for (int mi = 0; mi < 2; mi++)
#pragma unroll
                for (int nj = 0; nj < 4; nj++) {
                    MMA_TF32(d[mi][nj], ah[mi], bh[nj]);
                    MMA_TF32(d[mi][nj], ah[mi], bl[nj]);
                    MMA_TF32(d[mi][nj], al[mi], bh[nj]);
                }
        }

        if (s + 1 < ns) {
            char* nbuf = smc + ((s + 1) & 1) * GBUF;
            *(float4*)(nbuf + GA_H + soff) = pa0;
            *(float4*)(nbuf + GA_L + soff) = pa1;
            *(float4*)(nbuf + GB_H + soff) = pb0;
            *(float4*)(nbuf + GB_L + soff) = pb1;
            __syncthreads();
        }
    }

#pragma unroll
    for (int mi = 0; mi < 2; mi++)
#pragma unroll
        for (int nj = 0; nj < 4; nj++)
#pragma unroll
            for (int hf = 0; hf < 2; hf++) {
                const int m   = bm + wm * 32 + mi * 16 + gid + hf * 8;
                const int col = bn + wn * 32 + nj * 8 + tig * 2;
                const float v0 = d[mi][nj][hf * 2 + 0];
                const float v1 = d[mi][nj][hf * 2 + 1];
                if (mode == 0) {
                    const int h  = col >> 6;
                    const int d0 = col & 63;
                    const int b_ = m >> 10, n_ = m & 1023;
                    float* dst = g_v + ((size_t)((b_ * HEADS + h) << 10) + n_) * HD + d0;
                    *(float2*)dst = make_float2(v0, v1);
                } else {
                    float* dst = out + (size_t)m * DIM + col;
                    *(float2*)dst = make_float2(v0 + bias[col], v1 + bias[col + 1]);
                }
            }
}

// ---------------------------------------------------------------------------
// 3xTF32 S-GEMM (R8-PROVEN VERBATIM): S = Q @ K^T per head, K=64 smem-resident,
// fp32 q/k in smem, tf32 split in-loop. 70KB smem.
// ---------------------------------------------------------------------------
#define SSTR 68
#define S_SMEM (2*128*SSTR*4)     // 69632 B

__global__ __launch_bounds__(512)
void mma_s_tf32()
{
    extern __shared__ float sm[];
    float* Qs = sm;                 // [128][SSTR]
    float* Ks = sm + 128 * SSTR;

    const int tid  = threadIdx.x;
    const int wid  = tid >> 5;
    const int lane = tid & 31;
    const int gid  = lane >> 2;
    const int tig  = lane & 3;
    const int wm   = wid & 3;
    const int wn   = wid >> 2;
    const int bm   = blockIdx.y * 128;
    const int bn   = blockIdx.x * 128;
    const int head = blockIdx.z;

    const float* q = g_q + (size_t)head * NSEQ * HD;
    const float* k = g_k + (size_t)head * NSEQ * HD;

#pragma unroll
    for (int t = 0; t < 4; t++) {
        int id  = tid + t * 512;
        int row = id >> 4;
        int c4  = (id & 15) * 4;
        *(float4*)&Qs[row * SSTR + c4] = *(const float4*)(q + (size_t)(bm + row) * HD + c4);
        *(float4*)&Ks[row * SSTR + c4] = *(const float4*)(k + (size_t)(bn + row) * HD + c4);
    }
    __syncthreads();

    float d[2][4][4];
#pragma unroll
    for (int mi = 0; mi < 2; mi++)
#pragma unroll
        for (int nj = 0; nj < 4; nj++)
#pragma unroll
            for (int e = 0; e < 4; e++) d[mi][nj][e] = 0.f;

#pragma unroll
    for (int ks = 0; ks < 8; ks++) {
        const int k0 = ks * 8;
        uint32_t ah[2][4], al[2][4];
#pragma unroll
        for (int mi = 0; mi < 2; mi++) {
            int r0 = wm * 32 + mi * 16 + gid;
            tf32_split_u(Qs[r0 * SSTR + k0 + tig],           ah[mi][0], al[mi][0]);
            tf32_split_u(Qs[(r0 + 8) * SSTR + k0 + tig],     ah[mi][1], al[mi][1]);
            tf32_split_u(Qs[r0 * SSTR + k0 + tig + 4],       ah[mi][2], al[mi][2]);
            tf32_split_u(Qs[(r0 + 8) * SSTR + k0 + tig + 4], ah[mi][3], al[mi][3]);
        }
        uint32_t bh[4][2], bl[4][2];
#pragma unroll
        for (int nj = 0; nj < 4; nj++) {
            int n = wn * 32 + nj * 8 + gid;
            tf32_split_u(Ks[n * SSTR + k0 + tig],     bh[nj][0], bl[nj][0]);
            tf32_split_u(Ks[n * SSTR + k0 + tig + 4], bh[nj][1], bl[nj][1]);
        }

#pragma unroll
        for (int mi = 0; mi < 2; mi++)
#pragma unroll
            for (int nj = 0; nj < 4; nj++) {
                MMA_TF32(d[mi][nj], ah[mi], bh[nj]);
                MMA_TF32(d[mi][nj], ah[mi], bl[nj]);
                MMA_TF32(d[mi][nj], al[mi], bh[nj]);
            }
    }

    float* sdst = g_s + (size_t)head * NSEQ * NSEQ;
#pragma unroll
    for (int mi = 0; mi < 2; mi++)
#pragma unroll
        for (int nj = 0; nj < 4; nj++)
#pragma unroll
            for (int hf = 0; hf < 2; hf++) {
                const int m   = bm + wm * 32 + mi * 16 + gid + hf * 8;
                const int col = bn + wn * 32 + nj * 8 + tig * 2;
                *(float2*)(sdst + (size_t)m * NSEQ + col) =
                    make_float2(d[mi][nj][hf * 2 + 0], d[mi][nj][hf * 2 + 1]);
            }
}

// ---------------------------------------------------------------------------
// top-k + softmax + compaction: uint keys precomputed once, redux.sync
// reductions, float4 row loads. Same exact semantics as proven version.
// ---------------------------------------------------------------------------
__global__ __launch_bounds__(256)
void topk_kernel()
{
    const int head = blockIdx.y;
    const int warp = threadIdx.x >> 5;
    const int lane = threadIdx.x & 31;
    const int n    = blockIdx.x * 8 + warp;
    const size_t rbase = (size_t)head * NSEQ + n;
    const float4* srow4 = (const float4*)(g_s + rbase * NSEQ);

    float s[32];
    unsigned u[32];
#pragma unroll
    for (int i4 = 0; i4 < 8; i4++) {
        float4 v = srow4[i4 * 32 + lane];
        s[i4*4+0] = v.x; s[i4*4+1] = v.y; s[i4*4+2] = v.z; s[i4*4+3] = v.w;
        u[i4*4+0] = f2ord(v.x); u[i4*4+1] = f2ord(v.y);
        u[i4*4+2] = f2ord(v.z); u[i4*4+3] = f2ord(v.w);
    }

    // binary search on keys: largest t with count(u >= t) >= TOPK
    unsigned lo = 0x007FFFFFu;
    unsigned hi = 0xFF800000u;
    while (lo < hi) {
        unsigned mid = lo + ((hi - lo + 1u) >> 1);
        int cnt = 0;
#pragma unroll
        for (int i = 0; i < 32; i++) cnt += (u[i] >= mid) ? 1 : 0;
        cnt = redux_add(cnt);
        if (cnt >= TOPK) lo = mid; else hi = mid - 1u;
    }
    const unsigned kthu = lo;

    // max via key max (monotone)
    unsigned um = u[0];
#pragma unroll
    for (int i = 1; i < 32; i++) um = (u[i] > um) ? u[i] : um;
    um = redux_max_u(um);
    const float m = ord2f(um);

    float sum = 0.f;
    float p[32];
#pragma unroll
    for (int i = 0; i < 32; i++) {
        bool keep = (u[i] >= kthu);
        p[i] = keep ? __expf(s[i] - m) : 0.f;
        sum += p[i];
    }
#pragma unroll
    for (int o = 16; o > 0; o >>= 1)
        sum += __shfl_xor_sync(0xffffffffu, sum, o);
    const float inv = 1.f / sum;

    int* oidx = g_idx + rbase * CAP;
    float* opv = g_pv + rbase * CAP;
    int base = 0;
#pragma unroll
    for (int i = 0; i < 32; i++) {
        bool keep = (p[i] > 0.f);
        unsigned msk = __ballot_sync(0xffffffffu, keep);
        int pos = base + __popc(msk & ((1u << lane) - 1u));
        if (keep && pos < CAP) {
            oidx[pos] = (i >> 2) * 128 + lane * 4 + (i & 3);   // float4 layout index
            opv[pos]  = p[i] * inv;
        }
        base += __popc(msk);
    }
    if (lane == 0) g_cnt[rbase] = (base < CAP) ? base : CAP;
}

// ---------------------------------------------------------------------------
// sparse PV (R12-PROVEN) -> attn hi/lo tf32 split
// ---------------------------------------------------------------------------
__global__ __launch_bounds__(256)
void pv_sparse_kernel()
{
    __shared__ int   sj[8][CAP];
    __shared__ float spv[8][CAP];

    const int head = blockIdx.y;
    const int warp = threadIdx.x >> 5;
    const int lane = threadIdx.x & 31;
    const int n    = blockIdx.x * 8 + warp;
    const size_t rbase = (size_t)head * NSEQ + n;

    const int cnt = g_cnt[rbase];
    const int* oidx = g_idx + rbase * CAP;
    const float* opv = g_pv + rbase * CAP;
    for (int i = lane; i < cnt; i += 32) {
        sj[warp][i]  = oidx[i];
        spv[warp][i] = opv[i];
    }
    __syncwarp();

    const float* V = g_v + (size_t)head * NSEQ * HD;
    float2 acc = make_float2(0.f, 0.f);
    const int d2 = lane * 2;

    int i = 0;
    for (; i + 4 <= cnt; i += 4) {
        int   j0 = sj[warp][i+0], j1 = sj[warp][i+1];
        int   j2 = sj[warp][i+2], j3 = sj[warp][i+3];
        float p0 = spv[warp][i+0], p1 = spv[warp][i+1];
        float p2 = spv[warp][i+2], p3 = spv[warp][i+3];
        float2 v0 = *(const float2*)(V + (size_t)j0 * HD + d2);
        float2 v1 = *(const float2*)(V + (size_t)j1 * HD + d2);
        float2 v2 = *(const float2*)(V + (size_t)j2 * HD + d2);
        float2 v3 = *(const float2*)(V + (size_t)j3 * HD + d2);
        acc.x += p0*v0.x + p1*v1.x + p2*v2.x + p3*v3.x;
        acc.y += p0*v0.y + p1*v1.y + p2*v2.y + p3*v3.y;
    }
    for (; i < cnt; i++) {
        int j = sj[warp][i];
        float pp = spv[warp][i];
        float2 v = *(const float2*)(V + (size_t)j * HD + d2);
        acc.x += pp * v.x;
        acc.y += pp * v.y;
    }

    const int b = head / HEADS;
    const int h = head - b * HEADS;
    const size_t o = ((size_t)(b * NSEQ + n)) * DIM + h * HD + d2;
    float h0, l0, h1, l1;
    tf32_split(acc.x, h0, l0);
    tf32_split(acc.y, h1, l1);
    *(float2*)(g_ahi + o) = make_float2(h0, h1);
    *(float2*)(g_alo + o) = make_float2(l0, l1);
}

// ---------------------------------------------------------------------------
extern "C" void kernel_launch(void* const* d_in, const int* in_sizes, int n_in,
                              void* d_out, int out_size)
{
    const float* x      = (const float*)d_in[0];
    const float* w_qkv  = (const float*)d_in[1];
    const float* w_proj = (const float*)d_in[2];
    const float* b_proj = (const float*)d_in[3];
    float* out = (float*)d_out;

    cudaFuncSetAttribute(mma_gemm_tf32,
                         cudaFuncAttributeMaxDynamicSharedMemorySize, G_SMEM);
    cudaFuncSetAttribute(mma_s_tf32,
                         cudaFuncAttributeMaxDynamicSharedMemorySize, S_SMEM);

    // 0) weight transposes + x split
    transpose_split_w<<<dim3(DIM / 32, DIM / 32), dim3(32, 8)>>>(w_proj, DIM, 0, 0);
    transpose_split_w<<<dim3(DIM / 32, DIM / 32), dim3(32, 8)>>>(w_qkv, QKV_N, 2 * DIM, 1);
    split_x_kernel<<<(MROWS * DIM / 4 + 255) / 256, 256>>>(x, MROWS * DIM / 4);

    // 1a) Q/K GEMM (fp32, proven) + scatter (q scaled)
    sgemm_qk<<<dim3(QK_N / BN, MROWS / BM), 256>>>(x, w_qkv, MROWS, DIM, QKV_N);

    // 1b) V GEMM (3xTF32, proven core) + scatter
    mma_gemm_tf32<<<dim3(DIM / 128, MROWS / 128), 512, G_SMEM>>>(0, nullptr, nullptr);

    // 2a) S = Q @ K^T per head (R8-proven)
    mma_s_tf32<<<dim3(NSEQ / 128, NSEQ / 128, NHEAD), 512, S_SMEM>>>();

    // 2b) top-k + softmax + compaction (uint keys + redux)
    topk_kernel<<<dim3(NSEQ / 8, NHEAD), 256>>>();

    // 2c) sparse PV gather -> attn hi/lo
    pv_sparse_kernel<<<dim3(NSEQ / 8, NHEAD), 256>>>();

    // 3) output projection + bias (3xTF32, proven)
    mma_gemm_tf32<<<dim3(DIM / 128, MROWS / 128), 512, G_SMEM>>>(1, b_proj, out);
}